// round 14
// baseline (speedup 1.0000x reference)
#include <cuda_runtime.h>
#include <cuda_fp16.h>

// GraphConv: out = (feat + scatter_sum(feat[src]*norm_l[src] -> dst)) * norm_r
// norm_l = rsqrt(max(out_deg,1)+1), norm_r = rsqrt(max(in_deg,1)+1)
// N=100000 nodes, D=64 f32 features, E=1.25M edges (int32 indices).
//
// R13: (a) messages pre-scaled by norm_l and quantized to fp16 -> gather
// traffic halved (320MB -> 160MB, the measured L2-BW bottleneck);
// (b) 3-launch scan replaced by one decoupled-lookback scan fused with
// norm computation + cursor seeding.

#define N_MAX 100000
#define E_MAX 1250000
#define D 64
#define CHUNK 1024
#define BTHREADS 256
#define MAX_BLOCKS 128       // ceil(N_MAX/CHUNK) = 98

__device__ int   g_outdeg[N_MAX];
__device__ int   g_indeg[N_MAX];
__device__ int   g_cursor[N_MAX];
__device__ int   g_row_start[N_MAX + 1];
__device__ float g_norml[N_MAX];
__device__ float g_normr[N_MAX];
__device__ int   g_edge_src[E_MAX];
__device__ __half2 g_hfeat[(size_t)N_MAX * 32];   // fp16(feat * norm_l), 12.8MB

// decoupled-lookback state (flag: 0=invalid, 1=aggregate ready, 2=prefix ready)
__device__ volatile int g_flag[MAX_BLOCKS];
__device__ volatile int g_aggv[MAX_BLOCKS];
__device__ volatile int g_pref[MAX_BLOCKS];

// ---------------------------------------------------------------------------
// 1) zero degree scratch + scan state
// ---------------------------------------------------------------------------
__global__ void k_zero(int n) {
    int stride = gridDim.x * blockDim.x;
    int i = blockIdx.x * blockDim.x + threadIdx.x;
    for (int j = i; j < n; j += stride) {
        g_outdeg[j] = 0;
        g_indeg[j]  = 0;
    }
    if (i < MAX_BLOCKS) g_flag[i] = 0;
}

// ---------------------------------------------------------------------------
// 2) degree counting, 2 edges per thread (int2 loads, int REDG)
// ---------------------------------------------------------------------------
__global__ void k_degree(const int* __restrict__ src,
                         const int* __restrict__ dst, int E) {
    int i = blockIdx.x * blockDim.x + threadIdx.x;
    int E2 = E >> 1;
    if (i < E2) {
        int2 s = reinterpret_cast<const int2*>(src)[i];
        int2 d = reinterpret_cast<const int2*>(dst)[i];
        atomicAdd(&g_outdeg[s.x], 1);
        atomicAdd(&g_outdeg[s.y], 1);
        atomicAdd(&g_indeg[d.x], 1);
        atomicAdd(&g_indeg[d.y], 1);
    } else if (i == E2 && (E & 1)) {
        atomicAdd(&g_outdeg[src[E - 1]], 1);
        atomicAdd(&g_indeg[dst[E - 1]], 1);
    }
}

// ---------------------------------------------------------------------------
// 3) fused scan (decoupled lookback) + norms + cursor seed.
//    grid = ceil(n/1024) = 98 blocks, 256 threads, 4 elems/thread.
//    All 98 blocks are co-resident (<=148 SMs) -> spin lookback is safe.
// ---------------------------------------------------------------------------
__global__ void k_scan_fused(int n, int E) {
    __shared__ int warp_sums[BTHREADS / 32];
    __shared__ int sh_offset;
    int b = blockIdx.x;
    int t = threadIdx.x;
    int i0 = b * CHUNK + t * 4;

    int v0 = (i0 + 0 < n) ? g_indeg[i0 + 0] : 0;
    int v1 = (i0 + 1 < n) ? g_indeg[i0 + 1] : 0;
    int v2 = (i0 + 2 < n) ? g_indeg[i0 + 2] : 0;
    int v3 = (i0 + 3 < n) ? g_indeg[i0 + 3] : 0;
    int tsum = v0 + v1 + v2 + v3;

    int lane = t & 31, wid = t >> 5;
    int x = tsum;
    #pragma unroll
    for (int off = 1; off < 32; off <<= 1) {
        int y = __shfl_up_sync(0xffffffffu, x, off);
        if (lane >= off) x += y;
    }
    if (lane == 31) warp_sums[wid] = x;
    __syncthreads();
    if (wid == 0) {
        int w = (lane < BTHREADS / 32) ? warp_sums[lane] : 0;
        #pragma unroll
        for (int off = 1; off < BTHREADS / 32; off <<= 1) {
            int y = __shfl_up_sync(0xffffffffu, w, off);
            if (lane >= off) w += y;
        }
        if (lane < BTHREADS / 32) warp_sums[lane] = w;
    }
    __syncthreads();

    int excl = x - tsum + (wid > 0 ? warp_sums[wid - 1] : 0);
    int block_total = warp_sums[BTHREADS / 32 - 1];

    // --- decoupled lookback (thread 0) ---
    if (t == 0) {
        if (b == 0) {
            g_pref[0] = block_total;
            __threadfence();
            g_flag[0] = 2;
            sh_offset = 0;
        } else {
            g_aggv[b] = block_total;
            __threadfence();
            g_flag[b] = 1;
            int running = 0;
            for (int p = b - 1; p >= 0; p--) {
                int f;
                do { f = g_flag[p]; } while (f == 0);
                if (f == 2) { running += g_pref[p]; break; }
                running += g_aggv[p];
            }
            g_pref[b] = running + block_total;
            __threadfence();
            g_flag[b] = 2;
            sh_offset = running;
        }
    }
    __syncthreads();
    int base = sh_offset + excl;

    // --- epilogue: row_start, cursor, norms ---
    #pragma unroll
    for (int k = 0; k < 4; k++) {
        int i = i0 + k;
        if (i < n) {
            int rs = base;
            g_row_start[i] = rs;
            g_cursor[i] = rs;
            g_norml[i] = rsqrtf(fmaxf((float)g_outdeg[i], 1.0f) + 1.0f);
            float ind = (k == 0) ? (float)v0 : (k == 1) ? (float)v1
                      : (k == 2) ? (float)v2 : (float)v3;
            g_normr[i] = rsqrtf(fmaxf(ind, 1.0f) + 1.0f);
        }
        base += (k == 0) ? v0 : (k == 1) ? v1 : (k == 2) ? v2 : v3;
    }
    if (b == 0 && t == 0) g_row_start[n] = E;
}

// ---------------------------------------------------------------------------
// 4) convert: hfeat = fp16(feat * norm_l). One thread per half2 (2 cols).
// ---------------------------------------------------------------------------
__global__ void k_convert(const float* __restrict__ feat, int n) {
    int i = blockIdx.x * blockDim.x + threadIdx.x;   // n*32 half2 elements
    int total = n << 5;
    if (i < total) {
        int node = i >> 5;
        float nl = g_norml[node];
        float2 f = reinterpret_cast<const float2*>(feat)[i];
        g_hfeat[i] = __float22half2_rn(make_float2(f.x * nl, f.y * nl));
    }
}

// ---------------------------------------------------------------------------
// 5) fill CSR edge list: bucket src ids by dst (cursor pre-seeded)
// ---------------------------------------------------------------------------
__global__ void k_fill(const int* __restrict__ src,
                       const int* __restrict__ dst, int E) {
    int i = blockIdx.x * blockDim.x + threadIdx.x;
    if (i < E) {
        int pos = atomicAdd(&g_cursor[dst[i]], 1);
        g_edge_src[pos] = src[i];
    }
}

// ---------------------------------------------------------------------------
// 6) aggregate: one warp per dst node. Lane l owns cols [2l, 2l+1] as one
//    half2 (4B) -> each edge gather is a single 128B coalesced wavefront
//    (half the L2 traffic of fp32). norm_l already folded into hfeat.
//    fp32 accumulate; fused self-connection + right-norm on store.
// ---------------------------------------------------------------------------
__global__ void k_aggregate(const float* __restrict__ feat,
                            float* __restrict__ out, int n) {
    int node = (blockIdx.x * blockDim.x + threadIdx.x) >> 5;
    int lane = threadIdx.x & 31;
    if (node >= n) return;

    int beg = g_row_start[node];
    int end = g_row_start[node + 1];

    float ax = 0.f, ay = 0.f;
    int j = beg;
    // 4 independent gathers in flight per iteration
    for (; j + 4 <= end; j += 4) {
        int s0 = __ldg(&g_edge_src[j + 0]);
        int s1 = __ldg(&g_edge_src[j + 1]);
        int s2 = __ldg(&g_edge_src[j + 2]);
        int s3 = __ldg(&g_edge_src[j + 3]);
        float2 v0 = __half22float2(g_hfeat[(s0 << 5) + lane]);
        float2 v1 = __half22float2(g_hfeat[(s1 << 5) + lane]);
        float2 v2 = __half22float2(g_hfeat[(s2 << 5) + lane]);
        float2 v3 = __half22float2(g_hfeat[(s3 << 5) + lane]);
        ax += v0.x + v1.x + v2.x + v3.x;
        ay += v0.y + v1.y + v2.y + v3.y;
    }
    for (; j < end; j++) {
        int s = __ldg(&g_edge_src[j]);
        float2 v = __half22float2(g_hfeat[(s << 5) + lane]);
        ax += v.x;
        ay += v.y;
    }

    float nr = g_normr[node];
    float2 f = *reinterpret_cast<const float2*>(feat + ((long)node << 6) + (lane << 1));
    float2 r;
    r.x = (f.x + ax) * nr;
    r.y = (f.y + ay) * nr;
    *reinterpret_cast<float2*>(out + ((long)node << 6) + (lane << 1)) = r;
}

extern "C" void kernel_launch(void* const* d_in, const int* in_sizes, int n_in,
                              void* d_out, int out_size) {
    const float* feat = (const float*)d_in[0];
    const int*   src  = (const int*)d_in[1];
    const int*   dst  = (const int*)d_in[2];
    float*       out  = (float*)d_out;

    int n = in_sizes[0] / D;      // 100000
    int E = in_sizes[1];          // 1250000
    int nb = (n + CHUNK - 1) / CHUNK;   // 98 scan blocks
    int E2 = (E >> 1) + 1;

    k_zero<<<256, 256>>>(n);
    k_degree<<<(E2 + 255) / 256, 256>>>(src, dst, E);
    k_scan_fused<<<nb, BTHREADS>>>(n, E);
    {
        int total = n << 5;       // n*32 half2
        k_convert<<<(total + 255) / 256, 256>>>(feat, n);
    }
    k_fill<<<(E + 255) / 256, 256>>>(src, dst, E);
    {
        long long threads = (long long)n * 32;
        int blocks = (int)((threads + 255) / 256);
        k_aggregate<<<blocks, 256>>>(feat, out, n);
    }
}

// round 16
// speedup vs baseline: 1.2897x; 1.2897x over previous
#include <cuda_runtime.h>

// GraphConv: out = (feat + scatter_sum(feat[src]*norm_l[src] -> dst)) * norm_r
// norm_l = rsqrt(max(out_deg,1)+1), norm_r = rsqrt(max(in_deg,1)+1)
// N=100000 nodes, D=64 f32 features, E=1.25M edges (int32 indices).
//
// CSR-by-dst counting sort + warp-per-node register aggregation (all fp32,
// aggregate measured at the L2-BW cap). R15: 5 launches instead of 7
// (zero folded into aggregate tail, scan2 folded into scan3), and k_fill's
// returning atomics replaced by ranks captured for free in k_degree.

#define N_MAX 100000
#define E_MAX 1250000
#define D 64
#define CHUNK 1024
#define BTHREADS 256
#define NB_MAX 128       // ceil(N_MAX/CHUNK) = 98

// NOTE: __device__ globals are zero-initialized at load; k_aggregate re-zeroes
// g_outdeg/g_indeg at its tail so every kernel_launch sees zeroed degrees.
__device__ int   g_outdeg[N_MAX];
__device__ int   g_indeg[N_MAX];
__device__ int   g_rank[E_MAX];        // edge's arrival rank within its dst
__device__ int   g_row_start[N_MAX + 1];
__device__ int   g_bsum[NB_MAX];
__device__ float g_norml[N_MAX];
__device__ float g_normr[N_MAX];
__device__ int   g_edge_src[E_MAX];

// ---------------------------------------------------------------------------
// 1) degree counting; the dst atomic's return value IS the edge's slot rank
// ---------------------------------------------------------------------------
__global__ void k_degree(const int* __restrict__ src,
                         const int* __restrict__ dst, int E) {
    int i = blockIdx.x * blockDim.x + threadIdx.x;
    if (i < E) {
        atomicAdd(&g_outdeg[src[i]], 1);
        g_rank[i] = atomicAdd(&g_indeg[dst[i]], 1);
    }
}

// ---------------------------------------------------------------------------
// 2a) scan pass 1: per-block local exclusive scan of indeg (1024/block),
//     partial prefixes -> g_row_start, block total -> g_bsum[b]
// ---------------------------------------------------------------------------
__global__ void k_scan1(int n) {
    __shared__ int warp_sums[BTHREADS / 32];
    int b = blockIdx.x;
    int t = threadIdx.x;
    int i0 = b * CHUNK + t * 4;

    int v0 = (i0 + 0 < n) ? g_indeg[i0 + 0] : 0;
    int v1 = (i0 + 1 < n) ? g_indeg[i0 + 1] : 0;
    int v2 = (i0 + 2 < n) ? g_indeg[i0 + 2] : 0;
    int v3 = (i0 + 3 < n) ? g_indeg[i0 + 3] : 0;
    int tsum = v0 + v1 + v2 + v3;

    int lane = t & 31, wid = t >> 5;
    int x = tsum;
    #pragma unroll
    for (int off = 1; off < 32; off <<= 1) {
        int y = __shfl_up_sync(0xffffffffu, x, off);
        if (lane >= off) x += y;
    }
    if (lane == 31) warp_sums[wid] = x;
    __syncthreads();
    if (wid == 0) {
        int w = (lane < BTHREADS / 32) ? warp_sums[lane] : 0;
        #pragma unroll
        for (int off = 1; off < BTHREADS / 32; off <<= 1) {
            int y = __shfl_up_sync(0xffffffffu, w, off);
            if (lane >= off) w += y;
        }
        if (lane < BTHREADS / 32) warp_sums[lane] = w;
    }
    __syncthreads();

    int excl = x - tsum + (wid > 0 ? warp_sums[wid - 1] : 0);
    if (i0 + 0 < n) g_row_start[i0 + 0] = excl;
    if (i0 + 1 < n) g_row_start[i0 + 1] = excl + v0;
    if (i0 + 2 < n) g_row_start[i0 + 2] = excl + v0 + v1;
    if (i0 + 3 < n) g_row_start[i0 + 3] = excl + v0 + v1 + v2;
    if (t == BTHREADS - 1) g_bsum[b] = excl + tsum;
}

// ---------------------------------------------------------------------------
// 2b) scan pass 2+3 merged: every block redundantly scans the <=128 block
//     sums in smem (cheap), then applies offsets + computes norms.
// ---------------------------------------------------------------------------
__global__ void k_scan23(int n, int E, int nb) {
    __shared__ int sb[NB_MAX];
    __shared__ int ws[4];
    int t = threadIdx.x;
    int lane = t & 31, wid = t >> 5;

    int v = (t < 128 && t < nb) ? g_bsum[t] : 0;
    int x = v;
    if (t < 128) {
        #pragma unroll
        for (int off = 1; off < 32; off <<= 1) {
            int y = __shfl_up_sync(0xffffffffu, x, off);
            if (lane >= off) x += y;
        }
        if (lane == 31) ws[wid] = x;
    }
    __syncthreads();
    if (t < 128) {
        int add = 0;
        for (int k = 0; k < wid; k++) add += ws[k];   // wid < 4
        if (t < nb) sb[t] = x + add - v;              // exclusive prefix
    }
    __syncthreads();

    int i = blockIdx.x * blockDim.x + t;
    if (i < n) {
        int rs = g_row_start[i] + sb[i >> 10];        // CHUNK = 1024
        g_row_start[i] = rs;
        g_norml[i] = rsqrtf(fmaxf((float)g_outdeg[i], 1.0f) + 1.0f);
        g_normr[i] = rsqrtf(fmaxf((float)g_indeg[i], 1.0f) + 1.0f);
    }
    if (i == 0) g_row_start[n] = E;
}

// ---------------------------------------------------------------------------
// 3) fill CSR edge list: pos = row_start[dst] + rank. No atomics.
// ---------------------------------------------------------------------------
__global__ void k_fill(const int* __restrict__ src,
                       const int* __restrict__ dst, int E) {
    int i = blockIdx.x * blockDim.x + threadIdx.x;
    if (i < E) {
        int pos = g_row_start[dst[i]] + g_rank[i];
        g_edge_src[pos] = src[i];
    }
}

// ---------------------------------------------------------------------------
// 4) aggregate: one warp per dst node, two edges per iteration.
//    Lanes 0-15 process even-offset edges, lanes 16-31 odd-offset edges;
//    each lane gathers one float4 (16 x 16B = 256B coalesced per edge,
//    L2-resident). Halves merged via shfl_xor(16). Fused store:
//    out = (feat + h) * norm_r. Tail re-zeroes degrees for the next replay.
// ---------------------------------------------------------------------------
__global__ void k_aggregate(const float* __restrict__ feat,
                            float* __restrict__ out, int n) {
    int node = (blockIdx.x * blockDim.x + threadIdx.x) >> 5;
    int lane = threadIdx.x & 31;
    if (node >= n) return;

    int half = lane >> 4;        // which edge of the pair
    int fl   = lane & 15;        // float4 chunk index

    int beg = g_row_start[node];
    int end = g_row_start[node + 1];

    float ax = 0.f, ay = 0.f, az = 0.f, aw = 0.f;

    int j = beg;
    for (; j + 4 <= end; j += 4) {
        int s0 = __ldg(&g_edge_src[j + half]);
        int s1 = __ldg(&g_edge_src[j + 2 + half]);
        float n0 = __ldg(&g_norml[s0]);
        float n1 = __ldg(&g_norml[s1]);
        float4 v0 = *reinterpret_cast<const float4*>(feat + ((long)s0 << 6) + (fl << 2));
        float4 v1 = *reinterpret_cast<const float4*>(feat + ((long)s1 << 6) + (fl << 2));
        ax += v0.x * n0 + v1.x * n1;
        ay += v0.y * n0 + v1.y * n1;
        az += v0.z * n0 + v1.z * n1;
        aw += v0.w * n0 + v1.w * n1;
    }
    if (j + 2 <= end) {
        int s = __ldg(&g_edge_src[j + half]);
        float nl = __ldg(&g_norml[s]);
        float4 v = *reinterpret_cast<const float4*>(feat + ((long)s << 6) + (fl << 2));
        ax += v.x * nl; ay += v.y * nl; az += v.z * nl; aw += v.w * nl;
        j += 2;
    }
    if (j < end && half == 0) {
        int s = __ldg(&g_edge_src[j]);
        float nl = __ldg(&g_norml[s]);
        float4 v = *reinterpret_cast<const float4*>(feat + ((long)s << 6) + (fl << 2));
        ax += v.x * nl; ay += v.y * nl; az += v.z * nl; aw += v.w * nl;
    }

    ax += __shfl_xor_sync(0xffffffffu, ax, 16);
    ay += __shfl_xor_sync(0xffffffffu, ay, 16);
    az += __shfl_xor_sync(0xffffffffu, az, 16);
    aw += __shfl_xor_sync(0xffffffffu, aw, 16);

    if (half == 0) {
        float nr = g_normr[node];
        float4 f = *reinterpret_cast<const float4*>(feat + ((long)node << 6) + (fl << 2));
        float4 r;
        r.x = (f.x + ax) * nr;
        r.y = (f.y + ay) * nr;
        r.z = (f.z + az) * nr;
        r.w = (f.w + aw) * nr;
        *reinterpret_cast<float4*>(out + ((long)node << 6) + (fl << 2)) = r;
    }

    // re-zero degree scratch for the next graph replay (invariant: degrees
    // are zero on entry to k_degree; __device__ globals start zeroed)
    if (lane == 0) {
        g_outdeg[node] = 0;
        g_indeg[node]  = 0;
    }
}

extern "C" void kernel_launch(void* const* d_in, const int* in_sizes, int n_in,
                              void* d_out, int out_size) {
    const float* feat = (const float*)d_in[0];
    const int*   src  = (const int*)d_in[1];
    const int*   dst  = (const int*)d_in[2];
    float*       out  = (float*)d_out;

    int n = in_sizes[0] / D;      // 100000
    int E = in_sizes[1];          // 1250000
    int nb = (n + CHUNK - 1) / CHUNK;   // 98 scan blocks

    k_degree<<<(E + 255) / 256, 256>>>(src, dst, E);
    k_scan1<<<nb, BTHREADS>>>(n);
    k_scan23<<<(n + 255) / 256, 256>>>(n, E, nb);
    k_fill<<<(E + 255) / 256, 256>>>(src, dst, E);
    {
        long long threads = (long long)n * 32;
        int blocks = (int)((threads + 255) / 256);
        k_aggregate<<<blocks, 256>>>(feat, out, n);
    }
}

// round 17
// speedup vs baseline: 1.7165x; 1.3310x over previous
#include <cuda_runtime.h>

// GraphConv: out = (feat + scatter_sum(feat[src]*norm_l[src] -> dst)) * norm_r
// norm_l = rsqrt(max(out_deg,1)+1), norm_r = rsqrt(max(in_deg,1)+1)
// N=100000 nodes, D=64 f32 features, E=1.25M edges (int32 indices).
//
// R17 = best measured stage from each prior round:
//   degree: int2 + non-returning REDG (R12)   scan: 2-launch merged (R15)
//   fill:   cursor-atomic (R12)               aggregate: R12 (L2-BW capped)
// Degrees re-zeroed in aggregate tail (zero-on-entry invariant, no k_zero).

#define N_MAX 100000
#define E_MAX 1250000
#define D 64
#define CHUNK 1024
#define BTHREADS 256
#define NB_MAX 128       // ceil(N_MAX/CHUNK) = 98

__device__ int   g_outdeg[N_MAX];     // zero-init at load; re-zeroed each call
__device__ int   g_indeg[N_MAX];
__device__ int   g_cursor[N_MAX];
__device__ int   g_row_start[N_MAX + 1];
__device__ int   g_bsum[NB_MAX];
__device__ float g_norml[N_MAX];
__device__ float g_normr[N_MAX];
__device__ int   g_edge_src[E_MAX];

// ---------------------------------------------------------------------------
// 1) degree counting, 2 edges per thread (int2 loads, fire-and-forget REDG)
// ---------------------------------------------------------------------------
__global__ void k_degree(const int* __restrict__ src,
                         const int* __restrict__ dst, int E) {
    int i = blockIdx.x * blockDim.x + threadIdx.x;
    int E2 = E >> 1;
    if (i < E2) {
        int2 s = reinterpret_cast<const int2*>(src)[i];
        int2 d = reinterpret_cast<const int2*>(dst)[i];
        atomicAdd(&g_outdeg[s.x], 1);
        atomicAdd(&g_outdeg[s.y], 1);
        atomicAdd(&g_indeg[d.x], 1);
        atomicAdd(&g_indeg[d.y], 1);
    } else if (i == E2 && (E & 1)) {
        atomicAdd(&g_outdeg[src[E - 1]], 1);
        atomicAdd(&g_indeg[dst[E - 1]], 1);
    }
}

// ---------------------------------------------------------------------------
// 2a) scan pass 1: per-block local exclusive scan of indeg (1024/block)
// ---------------------------------------------------------------------------
__global__ void k_scan1(int n) {
    __shared__ int warp_sums[BTHREADS / 32];
    int b = blockIdx.x;
    int t = threadIdx.x;
    int i0 = b * CHUNK + t * 4;

    int v0 = (i0 + 0 < n) ? g_indeg[i0 + 0] : 0;
    int v1 = (i0 + 1 < n) ? g_indeg[i0 + 1] : 0;
    int v2 = (i0 + 2 < n) ? g_indeg[i0 + 2] : 0;
    int v3 = (i0 + 3 < n) ? g_indeg[i0 + 3] : 0;
    int tsum = v0 + v1 + v2 + v3;

    int lane = t & 31, wid = t >> 5;
    int x = tsum;
    #pragma unroll
    for (int off = 1; off < 32; off <<= 1) {
        int y = __shfl_up_sync(0xffffffffu, x, off);
        if (lane >= off) x += y;
    }
    if (lane == 31) warp_sums[wid] = x;
    __syncthreads();
    if (wid == 0) {
        int w = (lane < BTHREADS / 32) ? warp_sums[lane] : 0;
        #pragma unroll
        for (int off = 1; off < BTHREADS / 32; off <<= 1) {
            int y = __shfl_up_sync(0xffffffffu, w, off);
            if (lane >= off) w += y;
        }
        if (lane < BTHREADS / 32) warp_sums[lane] = w;
    }
    __syncthreads();

    int excl = x - tsum + (wid > 0 ? warp_sums[wid - 1] : 0);
    if (i0 + 0 < n) g_row_start[i0 + 0] = excl;
    if (i0 + 1 < n) g_row_start[i0 + 1] = excl + v0;
    if (i0 + 2 < n) g_row_start[i0 + 2] = excl + v0 + v1;
    if (i0 + 3 < n) g_row_start[i0 + 3] = excl + v0 + v1 + v2;
    if (t == BTHREADS - 1) g_bsum[b] = excl + tsum;
}

// ---------------------------------------------------------------------------
// 2b) scan pass 2+3 merged: every block redundantly scans the <=128 block
//     sums in smem, applies offsets, seeds cursors, computes norms.
// ---------------------------------------------------------------------------
__global__ void k_scan23(int n, int E, int nb) {
    __shared__ int sb[NB_MAX];
    __shared__ int ws[4];
    int t = threadIdx.x;
    int lane = t & 31, wid = t >> 5;

    int v = (t < 128 && t < nb) ? g_bsum[t] : 0;
    int x = v;
    if (t < 128) {
        #pragma unroll
        for (int off = 1; off < 32; off <<= 1) {
            int y = __shfl_up_sync(0xffffffffu, x, off);
            if (lane >= off) x += y;
        }
        if (lane == 31) ws[wid] = x;
    }
    __syncthreads();
    if (t < 128) {
        int add = 0;
        for (int k = 0; k < wid; k++) add += ws[k];   // wid < 4
        if (t < nb) sb[t] = x + add - v;              // exclusive prefix
    }
    __syncthreads();

    int i = blockIdx.x * blockDim.x + t;
    if (i < n) {
        int rs = g_row_start[i] + sb[i >> 10];        // CHUNK = 1024
        g_row_start[i] = rs;
        g_cursor[i] = rs;
        g_norml[i] = rsqrtf(fmaxf((float)g_outdeg[i], 1.0f) + 1.0f);
        g_normr[i] = rsqrtf(fmaxf((float)g_indeg[i], 1.0f) + 1.0f);
    }
    if (i == 0) g_row_start[n] = E;
}

// ---------------------------------------------------------------------------
// 3) fill CSR edge list: cursor atomic (pre-seeded with row starts)
// ---------------------------------------------------------------------------
__global__ void k_fill(const int* __restrict__ src,
                       const int* __restrict__ dst, int E) {
    int i = blockIdx.x * blockDim.x + threadIdx.x;
    if (i < E) {
        int pos = atomicAdd(&g_cursor[dst[i]], 1);
        g_edge_src[pos] = src[i];
    }
}

// ---------------------------------------------------------------------------
// 4) aggregate: one warp per dst node, two edges per iteration.
//    Lanes 0-15 process even-offset edges, lanes 16-31 odd-offset edges;
//    each lane gathers one float4 (16 x 16B = 256B coalesced per edge,
//    L2-resident). Halves merged via shfl_xor(16). Fused store:
//    out = (feat + h) * norm_r. Tail re-zeroes degrees for the next replay.
// ---------------------------------------------------------------------------
__global__ void k_aggregate(const float* __restrict__ feat,
                            float* __restrict__ out, int n) {
    int node = (blockIdx.x * blockDim.x + threadIdx.x) >> 5;
    int lane = threadIdx.x & 31;
    if (node >= n) return;

    int half = lane >> 4;        // which edge of the pair
    int fl   = lane & 15;        // float4 chunk index

    int beg = g_row_start[node];
    int end = g_row_start[node + 1];

    float ax = 0.f, ay = 0.f, az = 0.f, aw = 0.f;

    int j = beg;
    for (; j + 4 <= end; j += 4) {
        int s0 = __ldg(&g_edge_src[j + half]);
        int s1 = __ldg(&g_edge_src[j + 2 + half]);
        float n0 = __ldg(&g_norml[s0]);
        float n1 = __ldg(&g_norml[s1]);
        float4 v0 = *reinterpret_cast<const float4*>(feat + ((long)s0 << 6) + (fl << 2));
        float4 v1 = *reinterpret_cast<const float4*>(feat + ((long)s1 << 6) + (fl << 2));
        ax += v0.x * n0 + v1.x * n1;
        ay += v0.y * n0 + v1.y * n1;
        az += v0.z * n0 + v1.z * n1;
        aw += v0.w * n0 + v1.w * n1;
    }
    if (j + 2 <= end) {
        int s = __ldg(&g_edge_src[j + half]);
        float nl = __ldg(&g_norml[s]);
        float4 v = *reinterpret_cast<const float4*>(feat + ((long)s << 6) + (fl << 2));
        ax += v.x * nl; ay += v.y * nl; az += v.z * nl; aw += v.w * nl;
        j += 2;
    }
    if (j < end && half == 0) {
        int s = __ldg(&g_edge_src[j]);
        float nl = __ldg(&g_norml[s]);
        float4 v = *reinterpret_cast<const float4*>(feat + ((long)s << 6) + (fl << 2));
        ax += v.x * nl; ay += v.y * nl; az += v.z * nl; aw += v.w * nl;
    }

    ax += __shfl_xor_sync(0xffffffffu, ax, 16);
    ay += __shfl_xor_sync(0xffffffffu, ay, 16);
    az += __shfl_xor_sync(0xffffffffu, az, 16);
    aw += __shfl_xor_sync(0xffffffffu, aw, 16);

    if (half == 0) {
        float nr = g_normr[node];
        float4 f = *reinterpret_cast<const float4*>(feat + ((long)node << 6) + (fl << 2));
        float4 r;
        r.x = (f.x + ax) * nr;
        r.y = (f.y + ay) * nr;
        r.z = (f.z + az) * nr;
        r.w = (f.w + aw) * nr;
        *reinterpret_cast<float4*>(out + ((long)node << 6) + (fl << 2)) = r;
    }

    // re-zero degree scratch for the next graph replay (zero-on-entry
    // invariant; __device__ globals start zeroed for the first call)
    if (lane == 0) {
        g_outdeg[node] = 0;
        g_indeg[node]  = 0;
    }
}

extern "C" void kernel_launch(void* const* d_in, const int* in_sizes, int n_in,
                              void* d_out, int out_size) {
    const float* feat = (const float*)d_in[0];
    const int*   src  = (const int*)d_in[1];
    const int*   dst  = (const int*)d_in[2];
    float*       out  = (float*)d_out;

    int n = in_sizes[0] / D;      // 100000
    int E = in_sizes[1];          // 1250000
    int nb = (n + CHUNK - 1) / CHUNK;   // 98 scan blocks
    int E2 = (E >> 1) + 1;

    k_degree<<<(E2 + 255) / 256, 256>>>(src, dst, E);
    k_scan1<<<nb, BTHREADS>>>(n);
    k_scan23<<<(n + 255) / 256, 256>>>(n, E, nb);
    k_fill<<<(E + 255) / 256, 256>>>(src, dst, E);
    {
        long long threads = (long long)n * 32;
        int blocks = (int)((threads + 255) / 256);
        k_aggregate<<<blocks, 256>>>(feat, out, n);
    }
}